// round 5
// baseline (speedup 1.0000x reference)
#include <cuda_runtime.h>

#define BB 4
#define NN 8
#define HH 48
#define WW 48
#define HW (HH*WW)        /* 2304 */
#define TH 6
#define SMH (TH+6)
#define SMW (WW+6)

// Fused rank-1 kernel-prediction-network apply:
// pred_img_i[b,n,t,h,w] = 0.25 * sum_s W[b,n,s,t] * S_{K(s)},  K(s)=7,5,3,1
// S_K = sum_c sum_k c1[cur+k,c,t] * sum_l c2[cur+l,c,t] * F[c, h+k-r, w+l-r]
__global__ __launch_bounds__(WW*TH, 2)
void kpn_kernel(const float* __restrict__ frames,
                const float* __restrict__ core,
                const float* __restrict__ kw,
                float* __restrict__ out_i)
{
    const int tile = blockIdx.x;
    const int n    = blockIdx.y;
    const int b    = blockIdx.z;
    const int h0   = tile * TH;

    __shared__ float sF[4][SMH][SMW];   // 4*12*54*4 = 10368 B

    const int tid = threadIdx.x;

    // Cooperative load of the frames tile (zero-padded halo of 3)
    const float* fbase = frames + ((size_t)(b*NN + n)) * 4 * HW;
    for (int idx = tid; idx < 4*SMH*SMW; idx += WW*TH) {
        int c   = idx / (SMH*SMW);
        int rem = idx - c*(SMH*SMW);
        int i   = rem / SMW;
        int j   = rem - i*SMW;
        int hh  = h0 + i - 3;
        int wp  = j - 3;
        float v = 0.f;
        if ((unsigned)hh < HH && (unsigned)wp < WW)
            v = fbase[c*HW + hh*WW + wp];
        sF[c][i][j] = v;
    }
    __syncthreads();

    const int w   = tid % WW;
    const int ti  = tid / WW;            // 0..TH-1
    const int h   = h0 + ti;
    const int pix = h*WW + w;

    // core layout: [b][n*32 + q][color][rgb][h][w] flattened channels:
    // ch = ((q*4 + c)*3 + t), channel stride HW. q<16 -> c1, q>=16 -> c2.
    const float* cbase = core + (size_t)b*3072*HW + (size_t)n*384*HW + pix;

    float acc[4][3];                     // [K-group g: 0=K1,1=K3,2=K5,3=K7][t]
    #pragma unroll
    for (int g = 0; g < 4; g++)
        #pragma unroll
        for (int t = 0; t < 3; t++) acc[g][t] = 0.f;

    #pragma unroll 1
    for (int c = 0; c < 4; c++) {
        // 7x7 patch for this color, centered at (h,w), kept in registers
        float P[7][7];
        #pragma unroll
        for (int i = 0; i < 7; i++)
            #pragma unroll
            for (int j = 0; j < 7; j++)
                P[i][j] = sF[c][ti + i][w + j];

        #pragma unroll
        for (int t = 0; t < 3; t++) {
            // c2 (horizontal filter taps), q = 16..31
            float c2v[16];
            #pragma unroll
            for (int l = 0; l < 16; l++)
                c2v[l] = cbase[(size_t)(((16 + l)*4 + c)*3 + t) * HW];

            // g=0: K=1, cur=0, pad=3
            {
                float c1v = cbase[(size_t)((0*4 + c)*3 + t) * HW];
                acc[0][t] += c1v * (c2v[0] * P[3][3]);
            }
            // g=1: K=3, cur=1, pad=2
            #pragma unroll
            for (int k = 0; k < 3; k++) {
                float rs = c2v[1]*P[2+k][2] + c2v[2]*P[2+k][3] + c2v[3]*P[2+k][4];
                float c1v = cbase[(size_t)(((1 + k)*4 + c)*3 + t) * HW];
                acc[1][t] += c1v * rs;
            }
            // g=2: K=5, cur=4, pad=1
            #pragma unroll
            for (int k = 0; k < 5; k++) {
                float rs = 0.f;
                #pragma unroll
                for (int l = 0; l < 5; l++)
                    rs += c2v[4 + l] * P[1 + k][1 + l];
                float c1v = cbase[(size_t)(((4 + k)*4 + c)*3 + t) * HW];
                acc[2][t] += c1v * rs;
            }
            // g=3: K=7, cur=9, pad=0
            #pragma unroll
            for (int k = 0; k < 7; k++) {
                float rs = 0.f;
                #pragma unroll
                for (int l = 0; l < 7; l++)
                    rs += c2v[9 + l] * P[k][l];
                float c1v = cbase[(size_t)(((9 + k)*4 + c)*3 + t) * HW];
                acc[3][t] += c1v * rs;
            }
        }
    }

    // kernel_weight[b][n][s][t][h][w]; s=0 pairs with K=7 (stack order KS[::-1])
    const float* wb = kw + ((size_t)(b*NN + n)) * 4 * 3 * HW + pix;
    float* ob = out_i + ((size_t)(b*NN + n)) * 3 * HW + pix;
    #pragma unroll
    for (int t = 0; t < 3; t++) {
        float r = wb[(0*3 + t)*HW] * acc[3][t]
                + wb[(1*3 + t)*HW] * acc[2][t]
                + wb[(2*3 + t)*HW] * acc[1][t]
                + wb[(3*3 + t)*HW] * acc[0][t];
        ob[t*HW] = 0.25f * r;
    }
}

// pred_img = mean over n of pred_img_i
__global__ void mean_kernel(const float* __restrict__ in, float* __restrict__ outm)
{
    int idx = blockIdx.x * blockDim.x + threadIdx.x;   // B*3*H*W = 27648
    if (idx >= BB*3*HW) return;
    int b   = idx / (3*HW);
    int rem = idx - b*(3*HW);
    const float* p = in + (size_t)b*NN*3*HW + rem;
    float s = 0.f;
    #pragma unroll
    for (int n = 0; n < NN; n++) s += p[n*3*HW];
    outm[idx] = s * 0.125f;
}

extern "C" void kernel_launch(void* const* d_in, const int* in_sizes, int n_in,
                              void* d_out, int out_size)
{
    const float* frames = (const float*)d_in[0];
    const float* core   = (const float*)d_in[1];
    const float* kw     = (const float*)d_in[2];

    float* out   = (float*)d_out;
    float* out_i = out;                    // pred_img_i: (4,8,3,48,48) = 221184
    float* out_m = out + BB*NN*3*HW;       // pred_img:   (4,3,48,48)   =  27648

    dim3 grid(HH/TH, NN, BB);              // 8 x 8 x 4 = 256 blocks
    kpn_kernel<<<grid, WW*TH>>>(frames, core, kw, out_i);
    mean_kernel<<<(BB*3*HW + 255)/256, 256>>>(out_i, out_m);
}

// round 6
// speedup vs baseline: 1.0562x; 1.0562x over previous
#include <cuda_runtime.h>

#define BB 4
#define NN 8
#define HH 48
#define WW 48
#define HW (HH*WW)        /* 2304 */
#define TH 6
#define SMH (TH+6)
#define SMW (WW+6)
#define OUTM_ELEMS (BB*3*HW)   /* 27648 */

// Zero the pred_img accumulation region (float4 stores).
__global__ void zero_kernel(float4* __restrict__ p)
{
    int i = blockIdx.x * blockDim.x + threadIdx.x;
    if (i < OUTM_ELEMS/4) p[i] = make_float4(0.f, 0.f, 0.f, 0.f);
}

// Fused rank-1 kernel-prediction apply + n-mean accumulation.
// pred_img_i[b,n,t,h,w] = 0.25 * sum_s W[b,n,s,t] * S_{K(s)},  K(s)=7,5,3,1
// S_K = sum_c sum_k c1[cur+k,c,t] * sum_l c2[cur+l,c,t] * F[c, h+k-r, w+l-r]
// pred_img[b,t,h,w]   += pred_img_i / 8   (atomicAdd, zeroed beforehand)
__global__ __launch_bounds__(WW*TH, 2)
void kpn_kernel(const float* __restrict__ frames,
                const float* __restrict__ core,
                const float* __restrict__ kw,
                float* __restrict__ out_i,
                float* __restrict__ out_m)
{
    const int tile = blockIdx.x;
    const int n    = blockIdx.y;
    const int b    = blockIdx.z;
    const int h0   = tile * TH;

    __shared__ float sF[4][SMH][SMW];   // 10368 B

    const int tid = threadIdx.x;

    // Cooperative load of the frames tile (zero-padded halo of 3)
    const float* fbase = frames + ((size_t)(b*NN + n)) * 4 * HW;
    for (int idx = tid; idx < 4*SMH*SMW; idx += WW*TH) {
        int c   = idx / (SMH*SMW);
        int rem = idx - c*(SMH*SMW);
        int i   = rem / SMW;
        int j   = rem - i*SMW;
        int hh  = h0 + i - 3;
        int wp  = j - 3;
        float v = 0.f;
        if ((unsigned)hh < HH && (unsigned)wp < WW)
            v = fbase[c*HW + hh*WW + wp];
        sF[c][i][j] = v;
    }
    __syncthreads();

    const int w   = tid % WW;
    const int ti  = tid / WW;            // 0..TH-1
    const int h   = h0 + ti;
    const int pix = h*WW + w;

    // core channels: ch = ((q*4 + c)*3 + t), stride HW. q<16 -> c1, q>=16 -> c2.
    const float* cbase = core + (size_t)b*3072*HW + (size_t)n*384*HW + pix;

    float acc[4][3];                     // [K-group g: 0=K1,1=K3,2=K5,3=K7][t]
    #pragma unroll
    for (int g = 0; g < 4; g++)
        #pragma unroll
        for (int t = 0; t < 3; t++) acc[g][t] = 0.f;

    #pragma unroll 1
    for (int c = 0; c < 4; c++) {
        // 7x7 patch for this color, kept in registers, reused across t
        float P[7][7];
        #pragma unroll
        for (int i = 0; i < 7; i++)
            #pragma unroll
            for (int j = 0; j < 7; j++)
                P[i][j] = sF[c][ti + i][w + j];

        #pragma unroll
        for (int t = 0; t < 3; t++) {
            // Batch ALL 32 channel loads for this (c,t) up front -> max MLP
            float c1v[16], c2v[16];
            #pragma unroll
            for (int q = 0; q < 16; q++) {
                c1v[q] = cbase[(size_t)(((q     )*4 + c)*3 + t) * HW];
                c2v[q] = cbase[(size_t)(((16 + q)*4 + c)*3 + t) * HW];
            }

            // g=0: K=1, cur=0, pad=3
            acc[0][t] += c1v[0] * (c2v[0] * P[3][3]);

            // g=1: K=3, cur=1, pad=2
            #pragma unroll
            for (int k = 0; k < 3; k++) {
                float rs = c2v[1]*P[2+k][2] + c2v[2]*P[2+k][3] + c2v[3]*P[2+k][4];
                acc[1][t] += c1v[1 + k] * rs;
            }
            // g=2: K=5, cur=4, pad=1
            #pragma unroll
            for (int k = 0; k < 5; k++) {
                float rs = 0.f;
                #pragma unroll
                for (int l = 0; l < 5; l++)
                    rs += c2v[4 + l] * P[1 + k][1 + l];
                acc[2][t] += c1v[4 + k] * rs;
            }
            // g=3: K=7, cur=9, pad=0
            #pragma unroll
            for (int k = 0; k < 7; k++) {
                float rs = 0.f;
                #pragma unroll
                for (int l = 0; l < 7; l++)
                    rs += c2v[9 + l] * P[k][l];
                acc[3][t] += c1v[9 + k] * rs;
            }
        }
    }

    // kernel_weight[b][n][s][t][h][w]; s=0 pairs with K=7 (stack order KS[::-1])
    const float* wb = kw + ((size_t)(b*NN + n)) * 4 * 3 * HW + pix;
    float* ob = out_i + ((size_t)(b*NN + n)) * 3 * HW + pix;
    float* om = out_m + (size_t)b * 3 * HW + pix;
    #pragma unroll
    for (int t = 0; t < 3; t++) {
        float r = wb[(0*3 + t)*HW] * acc[3][t]
                + wb[(1*3 + t)*HW] * acc[2][t]
                + wb[(2*3 + t)*HW] * acc[1][t]
                + wb[(3*3 + t)*HW] * acc[0][t];
        ob[t*HW] = 0.25f * r;
        atomicAdd(om + t*HW, 0.03125f * r);   // 0.25 * (1/8)
    }
}

extern "C" void kernel_launch(void* const* d_in, const int* in_sizes, int n_in,
                              void* d_out, int out_size)
{
    const float* frames = (const float*)d_in[0];
    const float* core   = (const float*)d_in[1];
    const float* kw     = (const float*)d_in[2];

    float* out   = (float*)d_out;
    float* out_i = out;                    // pred_img_i: (4,8,3,48,48) = 221184
    float* out_m = out + BB*NN*3*HW;       // pred_img:   (4,3,48,48)   =  27648

    zero_kernel<<<(OUTM_ELEMS/4 + 255)/256, 256>>>((float4*)out_m);

    dim3 grid(HH/TH, NN, BB);              // 8 x 8 x 4 = 256 blocks
    kpn_kernel<<<grid, WW*TH>>>(frames, core, kw, out_i, out_m);
}